// round 7
// baseline (speedup 1.0000x reference)
#include <cuda_runtime.h>
#include <cuda_bf16.h>
#include <cstdint>
#include <math.h>

// ============================================================================
// W4A8B8O8 Linear.  y = round(a * (x @ W8^T) + b*bias) clamped to [-128,127],
// W8 = (unpack4(w) - zeros) * scales8 (per 128-col group). T=8192, IN=OUT=4096.
//
// Round 7 = clean re-run of round 6 (round 6 hit a container/infra failure and
// was never executed). KEY FIX under test: the harness's __output__ dtype set
// is {f32,i32,bf16} — int8 is promoted, so d_out is float32. Writing packed
// int8 bytes into it produced rel_err=nan in rounds 2-5. Epilogue stores
// float32 values. Inputs remain dtype-adaptive (detected on device).
// GEMM core: cp.async + ldmatrix + mma.sync.m16n8k32.s8 (tcgen05 is not
// available at the harness's compute_100 virtual arch).
// ============================================================================

constexpr int kT   = 8192;
constexpr int kIN  = 4096;
constexpr int kOUT = 4096;

constexpr int TM = 128, TN = 256, TK = 64;
constexpr int NKIT = kIN / TK;   // 64
constexpr int NSTG = 5;

constexpr int A_BYTES = TM * TK;             // 8192
constexpr int B_BYTES = TN * TK;             // 16384
constexpr int STG     = A_BYTES + B_BYTES;   // 24576

constexpr int SM_CV     = 0;                 // float2 cv[256] = {a[c], b*bias[c]}
constexpr int SM_STAGE0 = 2048;
constexpr int SMEM_TOTAL = SM_STAGE0 + NSTG * STG;   // 124928

// modes: 0 = raw int8, 1 = float32, 2 = int32, 3 = bfloat16  (input coercion)
__device__ int g_mode;
__device__ int g_a_first;    // first 4096-elem input is `a` (float)
__device__ int g_s_first;    // first 131072-elem input is scales8

__device__ __align__(16) int8_t g_x8[(size_t)kT * kIN];     // 32 MB
__device__ __align__(16) int8_t g_w8[(size_t)kOUT * kIN];   // 16 MB

// ============================= helpers ======================================

__device__ __forceinline__ uint32_t smem_u32(const void* p) {
    uint32_t r;
    asm("{ .reg .u64 t; cvta.to.shared.u64 t, %1; cvt.u32.u64 %0, t; }"
        : "=r"(r) : "l"(p));
    return r;
}

#define SWZ128(o) ((o) ^ (((o) >> 3) & 0x70))

__device__ __forceinline__ void cp16(uint32_t dst, const void* src) {
    asm volatile("cp.async.cg.shared.global [%0], [%1], 16;"
                 :: "r"(dst), "l"(src));
}
#define CP_COMMIT() asm volatile("cp.async.commit_group;" ::: "memory")
#define CP_WAIT(n)  asm volatile("cp.async.wait_group %0;" :: "n"(n) : "memory")

__device__ __forceinline__ void ldsm4(uint32_t& r0, uint32_t& r1,
                                      uint32_t& r2, uint32_t& r3, uint32_t a) {
    asm volatile("ldmatrix.sync.aligned.m8n8.x4.shared.b16 {%0,%1,%2,%3}, [%4];"
                 : "=r"(r0), "=r"(r1), "=r"(r2), "=r"(r3) : "r"(a));
}

__device__ __forceinline__ void mma_s8(int* c, const uint32_t* a, const uint32_t* b) {
    asm volatile(
        "mma.sync.aligned.m16n8k32.row.col.s32.s8.s8.s32 "
        "{%0,%1,%2,%3}, {%4,%5,%6,%7}, {%8,%9}, {%0,%1,%2,%3};"
        : "+r"(c[0]), "+r"(c[1]), "+r"(c[2]), "+r"(c[3])
        : "r"(a[0]), "r"(a[1]), "r"(a[2]), "r"(a[3]), "r"(b[0]), "r"(b[1]));
}

__device__ __forceinline__ int ld_int(const void* p, size_t i, int mode) {
    switch (mode) {
        case 0:  return ((const int8_t*)p)[i];
        case 1:  return (int)((const float*)p)[i];
        case 2:  return ((const int*)p)[i];
        default: return (int)__bfloat162float(((const __nv_bfloat16*)p)[i]);
    }
}
__device__ __forceinline__ int ld_ubyte(const void* p, size_t i, int mode) {
    switch (mode) {
        case 0:  return ((const uint8_t*)p)[i];
        case 1:  return (int)((const float*)p)[i];
        case 2:  return ((const int*)p)[i];
        default: return (int)__bfloat162float(((const __nv_bfloat16*)p)[i]);
    }
}

// ============================ input classify ================================
__global__ void classify_kernel(const void* px, const void* p4_0,
                                const void* p131_0) {
    const uint32_t* xw = (const uint32_t*)px;
    int i32ok = 1, f32ok = 1, bfok = 1;
#pragma unroll
    for (int i = 0; i < 16; i++) {
        uint32_t w = xw[i];
        int v = (int)w;
        i32ok &= (v >= -128 && v <= 127) ? 1 : 0;
        float f = __uint_as_float(w);
        f32ok &= (f == rintf(f) && fabsf(f) <= 255.0f) ? 1 : 0;
        uint32_t lo = w & 0xFFFF, hi = w >> 16;
        auto bfh = [](uint32_t h) {
            uint32_t e = h & 0x7F80u;
            return ((h & 0x7FFFu) == 0 || (e >= 0x3F80u && e < 0x4380u)) ? 1 : 0;
        };
        bfok &= bfh(lo) & bfh(hi);
    }
    g_mode = i32ok ? 2 : (f32ok ? 1 : (bfok ? 3 : 0));
    int mode = g_mode;

    // {a, bias}: `a` is genuine float32 in (1e-5, 2.1e-4]; any coercion of
    // bias fails this range when reinterpreted as float.
    const float* f = (const float*)p4_0;
    int ok = 1;
#pragma unroll
    for (int i = 0; i < 8; i++) {
        float v = f[i];
        ok &= (v > 8e-6f && v < 3e-4f) ? 1 : 0;
    }
    g_a_first = ok;

    // {scales8, zeros}: scales8 in [1,7]; zeros in [0,15].
    int ok2 = 1;
    for (int i = 0; i < 64; i++) {
        int v = ld_int(p131_0, i, mode);
        ok2 &= (v >= 1 && v <= 7) ? 1 : 0;
    }
    g_s_first = ok2;
}

// ========================= x materialization ================================
__global__ void __launch_bounds__(256)
xconv_kernel(const void* px) {
    const int mode = g_mode;
    size_t t = (size_t)blockIdx.x * 256 + threadIdx.x;
    int8_t* dst = g_x8 + t * 16;
    if (mode == 0) {
        *reinterpret_cast<uint4*>(dst) = ((const uint4*)px)[t];
    } else {
        int8_t r[16];
#pragma unroll
        for (int j = 0; j < 16; j++) r[j] = (int8_t)ld_int(px, t * 16 + j, mode);
        *reinterpret_cast<uint4*>(dst) = *reinterpret_cast<const uint4*>(r);
    }
}

// ============================ dequant pre-pass ==============================
// weight[o, i] packs cols 2i (low nibble), 2i+1 (high nibble).
__global__ void __launch_bounds__(256)
w4a8_dequant_kernel(const void* __restrict__ w,
                    const void* __restrict__ p131_0,
                    const void* __restrict__ p131_1) {
    const int mode = g_mode;
    const void* scales8 = g_s_first ? p131_0 : p131_1;
    const void* zeros   = g_s_first ? p131_1 : p131_0;
    int idx = blockIdx.x * blockDim.x + threadIdx.x;   // over kOUT * (kIN/8)
    int o  = idx >> 9;
    int c8 = idx & 511;
    int g  = c8 >> 4;
    int s  = ld_int(scales8, (size_t)o * (kIN / 128) + g, mode);
    int z  = ld_int(zeros,   (size_t)o * (kIN / 128) + g, mode);
    size_t wbase = (size_t)o * (kIN / 2) + c8 * 4;
    int8_t r[8];
#pragma unroll
    for (int j = 0; j < 4; j++) {
        int byte = ld_ubyte(w, wbase + j, mode);
        r[2 * j]     = (int8_t)(((byte & 0xF) - z) * s);
        r[2 * j + 1] = (int8_t)((((byte >> 4) & 0xF) - z) * s);
    }
    *reinterpret_cast<int2*>(g_w8 + (size_t)o * kIN + c8 * 8) =
        *reinterpret_cast<const int2*>(r);
}

// ================================ GEMM ======================================
__global__ void __launch_bounds__(256, 1)
w4a8_gemm_kernel(const void* __restrict__ p4_0,
                 const void* __restrict__ p4_1,
                 const float* __restrict__ bp,
                 float* __restrict__ outp) {        // f32 OUTPUT
    extern __shared__ char smem[];
    const int  mode  = g_mode;
    const void* biasp = g_a_first ? p4_1 : p4_0;
    const float* ap   = g_a_first ? (const float*)p4_0 : (const float*)p4_1;

    const int tid = threadIdx.x;
    const int wid = tid >> 5;
    const int lid = tid & 31;
    const int m0 = blockIdx.x * TM;
    const int n0 = blockIdx.y * TN;
    const uint32_t sbase = smem_u32(smem);

    // warp grid 2(M) x 4(N), warp tile 64x64
    const int mw = (wid >> 2) * 64;
    const int nw = (wid & 3) * 64;

    // per-channel requant constants cv[c] = {a[n0+c], b*bias[n0+c]}
    {
        float bval = *bp;
        for (int c = tid; c < TN; c += 256) {
            float av = ap[n0 + c];
            float bv = __fmul_rn((float)ld_int(biasp, n0 + c, mode), bval);
            reinterpret_cast<float2*>(smem + SM_CV)[c] = make_float2(av, bv);
        }
    }

    auto load_stage = [&](int s, int ki) {
        const int k0 = ki * TK;
        const uint32_t sa = sbase + SM_STAGE0 + s * STG;
        const uint32_t sb = sa + A_BYTES;
        const int8_t* ga = g_x8 + (size_t)m0 * kIN + k0;
        const int8_t* gb = g_w8 + (size_t)n0 * kIN + k0;
#pragma unroll
        for (int q = 0; q < 2; q++) {                      // A: 128x64B
            int idx = q * 256 + tid;
            int r = idx >> 2, c = (idx & 3) * 16;
            cp16(sa + SWZ128(r * 64 + c), ga + (size_t)r * kIN + c);
        }
#pragma unroll
        for (int q = 0; q < 4; q++) {                      // B: 256x64B
            int idx = q * 256 + tid;
            int r = idx >> 2, c = (idx & 3) * 16;
            cp16(sb + SWZ128(r * 64 + c), gb + (size_t)r * kIN + c);
        }
    };

    int acc[4][8][4] = {};   // 4 m16-tiles x 8 n8-tiles x 4 regs

    const int mtx = lid >> 3;   // ldmatrix matrix id
    const int lr  = lid & 7;    // row within matrix

    auto compute_stage = [&](int s) {
        const uint32_t sa = sbase + SM_STAGE0 + s * STG;
        const uint32_t sb = sa + A_BYTES;
#pragma unroll
        for (int ks = 0; ks < 2; ks++) {                   // two k32 steps
            uint32_t af[4][4], bf[8][2];
#pragma unroll
            for (int mt = 0; mt < 4; mt++) {
                int row = mw + mt * 16 + (mtx & 1) * 8 + lr;
                int kb  = ks * 32 + (mtx >> 1) * 16;
                ldsm4(af[mt][0], af[mt][1], af[mt][2], af[mt][3],
                      sa + SWZ128(row * 64 + kb));
            }
#pragma unroll
            for (int ng = 0; ng < 4; ng++) {               // n16 groups
                int row = nw + ng * 16 + (mtx >> 1) * 8 + lr;
                int kb  = ks * 32 + (mtx & 1) * 16;
                ldsm4(bf[2 * ng][0], bf[2 * ng][1],
                      bf[2 * ng + 1][0], bf[2 * ng + 1][1],
                      sb + SWZ128(row * 64 + kb));
            }
#pragma unroll
            for (int mt = 0; mt < 4; mt++)
#pragma unroll
                for (int nt = 0; nt < 8; nt++)
                    mma_s8(acc[mt][nt], af[mt], bf[nt]);
        }
    };

    // prologue
#pragma unroll
    for (int s = 0; s < NSTG - 1; s++) { load_stage(s, s); CP_COMMIT(); }

    // mainloop
    for (int i = 0; i < NKIT; i++) {
        CP_WAIT(NSTG - 2);
        __syncthreads();
        int nk = i + NSTG - 1;
        if (nk < NKIT) load_stage(nk % NSTG, nk);
        CP_COMMIT();
        compute_stage(i % NSTG);
    }
    __syncthreads();   // all compute done before epilogue reuses stage SMEM

    // -------- epilogue: requant -> int8 SMEM stage -> FLOAT32 stores --------
    const float2* cv = reinterpret_cast<const float2*>(smem + SM_CV);
    char* so = smem + SM_STAGE0;     // 32 KB int8 staging

    auto rq = [&](int v, float2 p) -> uint32_t {
        float t = __fmul_rn((float)v, p.x);      // match JAX: no FMA fusion
        float y = __fadd_rn(t, p.y);
        int q = __float2int_rn(y);               // round-half-even == jnp.round
        q = q < -128 ? -128 : (q > 127 ? 127 : q);
        return (uint32_t)q & 0xFF;
    };

#pragma unroll
    for (int mt = 0; mt < 4; mt++) {
        int r0 = mw + mt * 16 + (lid >> 2);
#pragma unroll
        for (int nt = 0; nt < 8; nt++) {
            int col = nw + nt * 8 + (lid & 3) * 2;
            float2 p0 = cv[col], p1 = cv[col + 1];
            uint16_t lo = (uint16_t)(rq(acc[mt][nt][0], p0) | (rq(acc[mt][nt][1], p1) << 8));
            uint16_t hi = (uint16_t)(rq(acc[mt][nt][2], p0) | (rq(acc[mt][nt][3], p1) << 8));
            *reinterpret_cast<uint16_t*>(so + r0 * 256 + col)       = lo;
            *reinterpret_cast<uint16_t*>(so + (r0 + 8) * 256 + col) = hi;
        }
    }
    __syncthreads();

#pragma unroll
    for (int q = 0; q < 8; q++) {                 // 16 values/thread -> f32
        int idx = q * 256 + tid;
        int row = idx >> 4, c = (idx & 15) * 16;
        const int8_t* src = reinterpret_cast<const int8_t*>(so + row * 256 + c);
        float* o = outp + (size_t)(m0 + row) * kOUT + n0 + c;
#pragma unroll
        for (int j = 0; j < 4; j++) {
            float4 v = make_float4((float)src[4 * j],     (float)src[4 * j + 1],
                                   (float)src[4 * j + 2], (float)src[4 * j + 3]);
            reinterpret_cast<float4*>(o)[j] = v;
        }
    }
}

// ============================== launch ======================================
extern "C" void kernel_launch(void* const* d_in, const int* in_sizes, int n_in,
                              void* d_out, int out_size) {
    const void* px = nullptr; const void* pw = nullptr; const void* pb = nullptr;
    const void* p4[2]   = {nullptr, nullptr};
    const void* p131[2] = {nullptr, nullptr};
    int n4 = 0, n131 = 0;
    for (int i = 0; i < n_in; i++) {
        long long s = in_sizes[i];
        if      (s == 33554432) px = d_in[i];
        else if (s == 8388608)  pw = d_in[i];
        else if (s == 1)        pb = d_in[i];
        else if (s == 4096)     { if (n4   < 2) p4[n4++]     = d_in[i]; }
        else if (s == 131072)   { if (n131 < 2) p131[n131++] = d_in[i]; }
    }
    // Binding miss -> launch nothing. Under the f32-output model this yields a
    // FINITE rel_err (~1.0) -- a distinguishable diagnostic vs nan.
    if (!px || !pw || !pb || n4 != 2 || n131 != 2) return;

    cudaFuncSetAttribute((const void*)w4a8_gemm_kernel,
                         cudaFuncAttributeMaxDynamicSharedMemorySize, SMEM_TOTAL);

    classify_kernel<<<1, 1>>>(px, p4[0], p131[0]);

    xconv_kernel<<<(kT * kIN / 16) / 256, 256>>>(px);

    w4a8_dequant_kernel<<<(kOUT * (kIN / 8)) / 256, 256>>>(pw, p131[0], p131[1]);

    dim3 grid(kT / TM, kOUT / TN);
    w4a8_gemm_kernel<<<grid, 256, SMEM_TOTAL>>>(p4[0], p4[1],
                                                (const float*)pb, (float*)d_out);
}

// round 8
// speedup vs baseline: 1.3187x; 1.3187x over previous
#include <cuda_runtime.h>
#include <cuda_bf16.h>
#include <cstdint>
#include <math.h>

// ============================================================================
// W4A8B8O8 Linear.  y = round(a * (x @ W8^T) + b*bias) clamped to [-128,127],
// W8 = (unpack4(w) - zeros) * scales8 (per 128-col group). T=8192, IN=OUT=4096.
// Output buffer is float32 (harness promotes int8) — confirmed round 7.
//
// Round 8: tensor pipe was 52.7% (memory idle: DRAM 3.9%, L2 16.4%).
//  (1) register-level fragment double-buffering so ldmatrix overlaps mma and
//      the stage barrier is covered by in-flight MMAs;
//  (2) skip the x copy pass when x arrives as raw int8 (GEMM reads px direct).
// ============================================================================

constexpr int kT   = 8192;
constexpr int kIN  = 4096;
constexpr int kOUT = 4096;

constexpr int TM = 128, TN = 256, TK = 64;
constexpr int NKIT = kIN / TK;   // 64
constexpr int NSTG = 5;

constexpr int A_BYTES = TM * TK;             // 8192
constexpr int B_BYTES = TN * TK;             // 16384
constexpr int STG     = A_BYTES + B_BYTES;   // 24576

constexpr int SM_CV     = 0;                 // float2 cv[256] = {a[c], b*bias[c]}
constexpr int SM_STAGE0 = 2048;
constexpr int SMEM_TOTAL = SM_STAGE0 + NSTG * STG;   // 124928

// modes: 0 = raw int8, 1 = float32, 2 = int32, 3 = bfloat16  (input coercion)
__device__ int g_mode;
__device__ int g_a_first;    // first 4096-elem input is `a` (float)
__device__ int g_s_first;    // first 131072-elem input is scales8

__device__ __align__(16) int8_t g_x8[(size_t)kT * kIN];     // 32 MB
__device__ __align__(16) int8_t g_w8[(size_t)kOUT * kIN];   // 16 MB

// ============================= helpers ======================================

__device__ __forceinline__ uint32_t smem_u32(const void* p) {
    uint32_t r;
    asm("{ .reg .u64 t; cvta.to.shared.u64 t, %1; cvt.u32.u64 %0, t; }"
        : "=r"(r) : "l"(p));
    return r;
}

#define SWZ128(o) ((o) ^ (((o) >> 3) & 0x70))

__device__ __forceinline__ void cp16(uint32_t dst, const void* src) {
    asm volatile("cp.async.cg.shared.global [%0], [%1], 16;"
                 :: "r"(dst), "l"(src));
}
#define CP_COMMIT() asm volatile("cp.async.commit_group;" ::: "memory")
#define CP_WAIT(n)  asm volatile("cp.async.wait_group %0;" :: "n"(n) : "memory")

__device__ __forceinline__ void ldsm4(uint32_t& r0, uint32_t& r1,
                                      uint32_t& r2, uint32_t& r3, uint32_t a) {
    asm volatile("ldmatrix.sync.aligned.m8n8.x4.shared.b16 {%0,%1,%2,%3}, [%4];"
                 : "=r"(r0), "=r"(r1), "=r"(r2), "=r"(r3) : "r"(a));
}

__device__ __forceinline__ void mma_s8(int* c, const uint32_t* a, const uint32_t* b) {
    asm volatile(
        "mma.sync.aligned.m16n8k32.row.col.s32.s8.s8.s32 "
        "{%0,%1,%2,%3}, {%4,%5,%6,%7}, {%8,%9}, {%0,%1,%2,%3};"
        : "+r"(c[0]), "+r"(c[1]), "+r"(c[2]), "+r"(c[3])
        : "r"(a[0]), "r"(a[1]), "r"(a[2]), "r"(a[3]), "r"(b[0]), "r"(b[1]));
}

__device__ __forceinline__ int ld_int(const void* p, size_t i, int mode) {
    switch (mode) {
        case 0:  return ((const int8_t*)p)[i];
        case 1:  return (int)((const float*)p)[i];
        case 2:  return ((const int*)p)[i];
        default: return (int)__bfloat162float(((const __nv_bfloat16*)p)[i]);
    }
}
__device__ __forceinline__ int ld_ubyte(const void* p, size_t i, int mode) {
    switch (mode) {
        case 0:  return ((const uint8_t*)p)[i];
        case 1:  return (int)((const float*)p)[i];
        case 2:  return ((const int*)p)[i];
        default: return (int)__bfloat162float(((const __nv_bfloat16*)p)[i]);
    }
}

// ============================ input classify ================================
__global__ void classify_kernel(const void* px, const void* p4_0,
                                const void* p131_0) {
    const uint32_t* xw = (const uint32_t*)px;
    int i32ok = 1, f32ok = 1, bfok = 1;
#pragma unroll
    for (int i = 0; i < 16; i++) {
        uint32_t w = xw[i];
        int v = (int)w;
        i32ok &= (v >= -128 && v <= 127) ? 1 : 0;
        float f = __uint_as_float(w);
        f32ok &= (f == rintf(f) && fabsf(f) <= 255.0f) ? 1 : 0;
        uint32_t lo = w & 0xFFFF, hi = w >> 16;
        auto bfh = [](uint32_t h) {
            uint32_t e = h & 0x7F80u;
            return ((h & 0x7FFFu) == 0 || (e >= 0x3F80u && e < 0x4380u)) ? 1 : 0;
        };
        bfok &= bfh(lo) & bfh(hi);
    }
    g_mode = i32ok ? 2 : (f32ok ? 1 : (bfok ? 3 : 0));
    int mode = g_mode;

    const float* f = (const float*)p4_0;
    int ok = 1;
#pragma unroll
    for (int i = 0; i < 8; i++) {
        float v = f[i];
        ok &= (v > 8e-6f && v < 3e-4f) ? 1 : 0;
    }
    g_a_first = ok;

    int ok2 = 1;
    for (int i = 0; i < 64; i++) {
        int v = ld_int(p131_0, i, mode);
        ok2 &= (v >= 1 && v <= 7) ? 1 : 0;
    }
    g_s_first = ok2;
}

// ========================= x materialization ================================
// Only needed when x was coerced; mode 0 reads px directly in the GEMM.
__global__ void __launch_bounds__(256)
xconv_kernel(const void* px) {
    const int mode = g_mode;
    if (mode == 0) return;
    size_t t = (size_t)blockIdx.x * 256 + threadIdx.x;
    int8_t r[16];
#pragma unroll
    for (int j = 0; j < 16; j++) r[j] = (int8_t)ld_int(px, t * 16 + j, mode);
    *reinterpret_cast<uint4*>(g_x8 + t * 16) = *reinterpret_cast<const uint4*>(r);
}

// ============================ dequant pre-pass ==============================
__global__ void __launch_bounds__(256)
w4a8_dequant_kernel(const void* __restrict__ w,
                    const void* __restrict__ p131_0,
                    const void* __restrict__ p131_1) {
    const int mode = g_mode;
    const void* scales8 = g_s_first ? p131_0 : p131_1;
    const void* zeros   = g_s_first ? p131_1 : p131_0;
    int idx = blockIdx.x * blockDim.x + threadIdx.x;
    int o  = idx >> 9;
    int c8 = idx & 511;
    int g  = c8 >> 4;
    int s  = ld_int(scales8, (size_t)o * (kIN / 128) + g, mode);
    int z  = ld_int(zeros,   (size_t)o * (kIN / 128) + g, mode);
    size_t wbase = (size_t)o * (kIN / 2) + c8 * 4;
    int8_t r[8];
#pragma unroll
    for (int j = 0; j < 4; j++) {
        int byte = ld_ubyte(w, wbase + j, mode);
        r[2 * j]     = (int8_t)(((byte & 0xF) - z) * s);
        r[2 * j + 1] = (int8_t)((((byte >> 4) & 0xF) - z) * s);
    }
    *reinterpret_cast<int2*>(g_w8 + (size_t)o * kIN + c8 * 8) =
        *reinterpret_cast<const int2*>(r);
}

// ================================ GEMM ======================================
__global__ void __launch_bounds__(256, 1)
w4a8_gemm_kernel(const void* __restrict__ pxin,
                 const void* __restrict__ p4_0,
                 const void* __restrict__ p4_1,
                 const float* __restrict__ bp,
                 float* __restrict__ outp) {
    extern __shared__ char smem[];
    const int  mode  = g_mode;
    const void* biasp = g_a_first ? p4_1 : p4_0;
    const float* ap   = g_a_first ? (const float*)p4_0 : (const float*)p4_1;
    const int8_t* xp  = (mode == 0) ? (const int8_t*)pxin : g_x8;

    const int tid = threadIdx.x;
    const int wid = tid >> 5;
    const int lid = tid & 31;
    const int m0 = blockIdx.x * TM;
    const int n0 = blockIdx.y * TN;
    const uint32_t sbase = smem_u32(smem);

    const int mw = (wid >> 2) * 64;     // warp grid 2(M) x 4(N), tile 64x64
    const int nw = (wid & 3) * 64;

    {   // per-channel requant constants cv[c] = {a[n0+c], b*bias[n0+c]}
        float bval = *bp;
        for (int c = tid; c < TN; c += 256) {
            float av = ap[n0 + c];
            float bv = __fmul_rn((float)ld_int(biasp, n0 + c, mode), bval);
            reinterpret_cast<float2*>(smem + SM_CV)[c] = make_float2(av, bv);
        }
    }

    auto load_stage = [&](int s, int ki) {
        const int k0 = ki * TK;
        const uint32_t sa = sbase + SM_STAGE0 + s * STG;
        const uint32_t sb = sa + A_BYTES;
        const int8_t* ga = xp   + (size_t)m0 * kIN + k0;
        const int8_t* gb = g_w8 + (size_t)n0 * kIN + k0;
#pragma unroll
        for (int q = 0; q < 2; q++) {                      // A: 128x64B
            int idx = q * 256 + tid;
            int r = idx >> 2, c = (idx & 3) * 16;
            cp16(sa + SWZ128(r * 64 + c), ga + (size_t)r * kIN + c);
        }
#pragma unroll
        for (int q = 0; q < 4; q++) {                      // B: 256x64B
            int idx = q * 256 + tid;
            int r = idx >> 2, c = (idx & 3) * 16;
            cp16(sb + SWZ128(r * 64 + c), gb + (size_t)r * kIN + c);
        }
    };

    int acc[4][8][4] = {};            // 4 m16 x 8 n8 x 4 regs
    uint32_t af[2][4][4], bf[2][8][2];   // double-buffered fragments

    const int mtx = lid >> 3;
    const int lr  = lid & 7;

    auto load_frags = [&](int buf, int s, int ks) {
        const uint32_t sa = sbase + SM_STAGE0 + s * STG;
        const uint32_t sb = sa + A_BYTES;
#pragma unroll
        for (int mt = 0; mt < 4; mt++) {
            int row = mw + mt * 16 + (mtx & 1) * 8 + lr;
            int kb  = ks * 32 + (mtx >> 1) * 16;
            ldsm4(af[buf][mt][0], af[buf][mt][1], af[buf][mt][2], af[buf][mt][3],
                  sa + SWZ128(row * 64 + kb));
        }
#pragma unroll
        for (int ng = 0; ng < 4; ng++) {
            int row = nw + ng * 16 + (mtx >> 1) * 8 + lr;
            int kb  = ks * 32 + (mtx & 1) * 16;
            ldsm4(bf[buf][2 * ng][0], bf[buf][2 * ng][1],
                  bf[buf][2 * ng + 1][0], bf[buf][2 * ng + 1][1],
                  sb + SWZ128(row * 64 + kb));
        }
    };

    auto mma_all = [&](int buf) {
#pragma unroll
        for (int mt = 0; mt < 4; mt++)
#pragma unroll
            for (int nt = 0; nt < 8; nt++)
                mma_s8(acc[mt][nt], af[buf][mt], bf[buf][nt]);
    };

    // prologue: prefetch NSTG-1 stages, then frags for (stage 0, ks 0)
#pragma unroll
    for (int s = 0; s < NSTG - 1; s++) { load_stage(s, s); CP_COMMIT(); }
    CP_WAIT(NSTG - 2);
    __syncthreads();
    load_frags(0, 0, 0);

    // mainloop: frag prefetch overlaps mma; barrier is covered by in-flight mma
    int sc = 0;               // stage slot being consumed
    int sw = NSTG - 1;        // stage slot to fill next
    int kn = NSTG - 1;        // next k-chunk index to fetch
    for (int i = 0; i < NKIT; i++) {
        // ks = 0: prefetch ks=1 frags of current stage, then mma ks=0
        load_frags(1, sc, 1);
        mma_all(0);
        // ks = 1: issue gmem loads for stage kn, barrier for stage i+1,
        // prefetch its ks=0 frags, then mma ks=1
        if (kn < NKIT) load_stage(sw, kn);
        CP_COMMIT();
        kn++;
        sw = (sw + 1 == NSTG) ? 0 : sw + 1;
        CP_WAIT(NSTG - 2);
        __syncthreads();
        sc = (sc + 1 == NSTG) ? 0 : sc + 1;
        if (i + 1 < NKIT) load_frags(0, sc, 0);
        mma_all(1);
    }
    __syncthreads();   // all compute done before epilogue reuses stage SMEM

    // -------- epilogue: requant -> int8 SMEM stage -> FLOAT32 stores --------
    const float2* cv = reinterpret_cast<const float2*>(smem + SM_CV);
    char* so = smem + SM_STAGE0;

    auto rq = [&](int v, float2 p) -> uint32_t {
        float t = __fmul_rn((float)v, p.x);      // match JAX: no FMA fusion
        float y = __fadd_rn(t, p.y);
        int q = __float2int_rn(y);               // round-half-even == jnp.round
        q = q < -128 ? -128 : (q > 127 ? 127 : q);
        return (uint32_t)q & 0xFF;
    };

#pragma unroll
    for (int mt = 0; mt < 4; mt++) {
        int r0 = mw + mt * 16 + (lid >> 2);
#pragma unroll
        for (int nt = 0; nt < 8; nt++) {
            int col = nw + nt * 8 + (lid & 3) * 2;
            float2 p0 = cv[col], p1 = cv[col + 1];
            uint16_t lo = (uint16_t)(rq(acc[mt][nt][0], p0) | (rq(acc[mt][nt][1], p1) << 8));
            uint16_t hi = (uint16_t)(rq(acc[mt][nt][2], p0) | (rq(acc[mt][nt][3], p1) << 8));
            *reinterpret_cast<uint16_t*>(so + r0 * 256 + col)       = lo;
            *reinterpret_cast<uint16_t*>(so + (r0 + 8) * 256 + col) = hi;
        }
    }
    __syncthreads();

#pragma unroll
    for (int q = 0; q < 8; q++) {                 // 16 values/thread -> f32
        int idx = q * 256 + tid;
        int row = idx >> 4, c = (idx & 15) * 16;
        const int8_t* src = reinterpret_cast<const int8_t*>(so + row * 256 + c);
        float* o = outp + (size_t)(m0 + row) * kOUT + n0 + c;
#pragma unroll
        for (int j = 0; j < 4; j++) {
            float4 v = make_float4((float)src[4 * j],     (float)src[4 * j + 1],
                                   (float)src[4 * j + 2], (float)src[4 * j + 3]);
            reinterpret_cast<float4*>(o)[j] = v;
        }
    }
}

// ============================== launch ======================================
extern "C" void kernel_launch(void* const* d_in, const int* in_sizes, int n_in,
                              void* d_out, int out_size) {
    const void* px = nullptr; const void* pw = nullptr; const void* pb = nullptr;
    const void* p4[2]   = {nullptr, nullptr};
    const void* p131[2] = {nullptr, nullptr};
    int n4 = 0, n131 = 0;
    for (int i = 0; i < n_in; i++) {
        long long s = in_sizes[i];
        if      (s == 33554432) px = d_in[i];
        else if (s == 8388608)  pw = d_in[i];
        else if (s == 1)        pb = d_in[i];
        else if (s == 4096)     { if (n4   < 2) p4[n4++]     = d_in[i]; }
        else if (s == 131072)   { if (n131 < 2) p131[n131++] = d_in[i]; }
    }
    if (!px || !pw || !pb || n4 != 2 || n131 != 2) return;

    cudaFuncSetAttribute((const void*)w4a8_gemm_kernel,
                         cudaFuncAttributeMaxDynamicSharedMemorySize, SMEM_TOTAL);

    classify_kernel<<<1, 1>>>(px, p4[0], p131[0]);

    xconv_kernel<<<(kT * kIN / 16) / 256, 256>>>(px);

    w4a8_dequant_kernel<<<(kOUT * (kIN / 8)) / 256, 256>>>(pw, p131[0], p131[1]);

    dim3 grid(kT / TM, kOUT / TN);
    w4a8_gemm_kernel<<<grid, 256, SMEM_TOTAL>>>(px, p4[0], p4[1],
                                                (const float*)pb, (float*)d_out);
}